// round 10
// baseline (speedup 1.0000x reference)
#include <cuda_runtime.h>
#include <math.h>

// ---------------- problem constants ----------------
#define ROWS      40960
#define CDIM      192
#define NWIN      320
#define BH        768
#define MLPH      768
#define QK_SCALE  0.17677669529663687f

// ---------------- scratch ----------------
__device__ float g_h [ (size_t)ROWS * CDIM ];
__device__ float g_q [ (size_t)BH * NWIN * 32 ];
__device__ float g_k [ (size_t)BH * NWIN * 32 ];
__device__ float g_v [ (size_t)BH * NWIN * 32 ];
__device__ float g_a [ (size_t)ROWS * CDIM ];
__device__ float g_x1[ (size_t)ROWS * CDIM ];
__device__ float g_g [ (size_t)ROWS * MLPH ];
__device__ float g_bias6[ 6 * NWIN * NWIN ];

__device__ __forceinline__ int winmap(int wr) {
    int b_ = wr / NWIN, n = wr - b_ * NWIN;
    int b  = b_ >> 6,  w = b_ & 63;
    int wh = w >> 3,   ww = w & 7;
    int t  = n >> 6;
    int rem = n & 63;
    int i = rem >> 3, j = rem & 7;
    int hs = (wh * 8 + i + 4) & 63;
    int ws = (ww * 8 + j + 4) & 63;
    return ((b * 5 + t) << 12) + (hs << 6) + ws;
}

// ---------------- relative-position bias precompute ----------------
__global__ void bias_kernel(const float* __restrict__ table) {
    int e = blockIdx.x * 1024 + threadIdx.x;
    if (e >= 6 * NWIN * NWIN) return;
    int head = e / (NWIN * NWIN);
    int r = e - head * (NWIN * NWIN);
    int n = r / NWIN, m = r - n * NWIN;
    int t1 = n >> 6, p1 = n & 63, i1 = p1 >> 3, j1 = p1 & 7;
    int t2 = m >> 6, p2 = m & 63, i2 = p2 >> 3, j2 = p2 & 7;
    int idx = (t1 - t2 + 7) * 15 + (i1 - i2 + 7) + (j1 - j2);
    g_bias6[e] = table[idx * 6 + head];
}

// ---------------- LayerNorm ----------------
template<int SRC>
__global__ __launch_bounds__(256) void ln_kernel(const float* __restrict__ in,
                                                 const float* __restrict__ gw,
                                                 const float* __restrict__ bw) {
    int row  = blockIdx.x * 8 + (threadIdx.x >> 5);
    int lane = threadIdx.x & 31;
    const float* src = (SRC == 0) ? in : g_x1;
    const float* p = src + (size_t)row * CDIM;
    float v[6];
    float s = 0.f;
#pragma unroll
    for (int u = 0; u < 6; u++) { v[u] = p[lane + 32 * u]; s += v[u]; }
#pragma unroll
    for (int o = 16; o; o >>= 1) s += __shfl_xor_sync(0xffffffffu, s, o);
    float mu = s * (1.0f / CDIM);
    float q = 0.f;
#pragma unroll
    for (int u = 0; u < 6; u++) { float d = v[u] - mu; q += d * d; }
#pragma unroll
    for (int o = 16; o; o >>= 1) q += __shfl_xor_sync(0xffffffffu, q, o);
    float rs = rsqrtf(q * (1.0f / CDIM) + 1e-5f);
    float* o = g_h + (size_t)row * CDIM;
#pragma unroll
    for (int u = 0; u < 6; u++) {
        int c = lane + 32 * u;
        o[c] = (v[u] - mu) * rs * gw[c] + bw[c];
    }
}

// ---------------- GEMM epilogues ----------------
struct EpiQKV {
    __device__ void operator()(int wr, int oc, float val) const {
        int which = oc / CDIM;
        int rem = oc - which * CDIM;
        int h = rem >> 5, d = rem & 31;
        int b_ = wr / NWIN, n = wr - b_ * NWIN;
        size_t off = ((size_t)(b_ * 6 + h)) * (NWIN * 32) + (size_t)n * 32 + d;
        if (which == 0)      g_q[off] = val * QK_SCALE;
        else if (which == 1) g_k[off] = val;
        else                 g_v[off] = val;
    }
};
struct EpiProj {
    const float* x;
    __device__ void operator()(int wr, int c, float v) const {
        int dst = winmap(wr);
        size_t o = (size_t)dst * CDIM + c;
        g_x1[o] = x[o] + v;
    }
};
struct EpiGelu {
    __device__ void operator()(int r, int c, float v) const {
        g_g[(size_t)r * MLPH + c] = 0.5f * v * (1.0f + erff(v * 0.7071067811865476f));
    }
};
struct EpiOut {
    float* out;
    __device__ void operator()(int r, int c, float v) const {
        size_t o = (size_t)r * CDIM + c;
        out[o] = g_x1[o] + v;
    }
};

// ---------------- 128x64x16 SGEMM, 128 threads, 8x8 microtile, double-buffered ----
template<int ASRC, bool GATHER, class Epi>
__global__ __launch_bounds__(128) void gemm128(const float* __restrict__ Aparam,
                                               const float* __restrict__ W,
                                               const float* __restrict__ bias,
                                               int K, Epi epi) {
    const float* A = (ASRC == 0) ? Aparam : (ASRC == 1) ? g_h : (ASRC == 2) ? g_a : g_g;
    __shared__ float As[2][16 * 132];
    __shared__ float Bs[2][16 * 68];
    int tid = threadIdx.x, bm = blockIdx.y, bn = blockIdx.x;
    int tx = tid & 7, ty = tid >> 3;

    int arow = bm * 128 + tid;
    int asrc = GATHER ? winmap(arow) : arow;
    const float* Ap = A + (size_t)asrc * K;
    int brow = tid >> 1, bkq = (tid & 1) * 8;
    const float* Wp = W + (size_t)(bn * 64 + brow) * K + bkq;

    float4 a0, a1, a2, a3, b0, b1;
    a0 = *(const float4*)(Ap + 0);
    a1 = *(const float4*)(Ap + 4);
    a2 = *(const float4*)(Ap + 8);
    a3 = *(const float4*)(Ap + 12);
    b0 = *(const float4*)(Wp + 0);
    b1 = *(const float4*)(Wp + 4);

    {
        float* as = As[0];
        as[ 0*132+tid]=a0.x; as[ 1*132+tid]=a0.y; as[ 2*132+tid]=a0.z; as[ 3*132+tid]=a0.w;
        as[ 4*132+tid]=a1.x; as[ 5*132+tid]=a1.y; as[ 6*132+tid]=a1.z; as[ 7*132+tid]=a1.w;
        as[ 8*132+tid]=a2.x; as[ 9*132+tid]=a2.y; as[10*132+tid]=a2.z; as[11*132+tid]=a2.w;
        as[12*132+tid]=a3.x; as[13*132+tid]=a3.y; as[14*132+tid]=a3.z; as[15*132+tid]=a3.w;
        float* bs = Bs[0];
        bs[(bkq+0)*68+brow]=b0.x; bs[(bkq+1)*68+brow]=b0.y;
        bs[(bkq+2)*68+brow]=b0.z; bs[(bkq+3)*68+brow]=b0.w;
        bs[(bkq+4)*68+brow]=b1.x; bs[(bkq+5)*68+brow]=b1.y;
        bs[(bkq+6)*68+brow]=b1.z; bs[(bkq+7)*68+brow]=b1.w;
    }
    __syncthreads();

    float acc[8][8] = {};
    int nt = K >> 4;
    for (int t = 0; t < nt; t++) {
        int cur = t & 1;
        if (t + 1 < nt) {
            const float* Ap2 = Ap + (t + 1) * 16;
            const float* Wp2 = Wp + (t + 1) * 16;
            a0 = *(const float4*)(Ap2 + 0);
            a1 = *(const float4*)(Ap2 + 4);
            a2 = *(const float4*)(Ap2 + 8);
            a3 = *(const float4*)(Ap2 + 12);
            b0 = *(const float4*)(Wp2 + 0);
            b1 = *(const float4*)(Wp2 + 4);
        }
        const float* as = As[cur];
        const float* bs = Bs[cur];
#pragma unroll
        for (int kk = 0; kk < 16; kk++) {
            float4 av0 = *(const float4*)&as[kk * 132 + ty * 8];
            float4 av1 = *(const float4*)&as[kk * 132 + ty * 8 + 4];
            float4 bv0 = *(const float4*)&bs[kk * 68 + tx * 8];
            float4 bv1 = *(const float4*)&bs[kk * 68 + tx * 8 + 4];
            float av[8] = {av0.x, av0.y, av0.z, av0.w, av1.x, av1.y, av1.z, av1.w};
            float bv[8] = {bv0.x, bv0.y, bv0.z, bv0.w, bv1.x, bv1.y, bv1.z, bv1.w};
#pragma unroll
            for (int i = 0; i < 8; i++)
#pragma unroll
                for (int j = 0; j < 8; j++) acc[i][j] += av[i] * bv[j];
        }
        if (t + 1 < nt) {
            int nxt = cur ^ 1;
            float* asw = As[nxt];
            asw[ 0*132+tid]=a0.x; asw[ 1*132+tid]=a0.y; asw[ 2*132+tid]=a0.z; asw[ 3*132+tid]=a0.w;
            asw[ 4*132+tid]=a1.x; asw[ 5*132+tid]=a1.y; asw[ 6*132+tid]=a1.z; asw[ 7*132+tid]=a1.w;
            asw[ 8*132+tid]=a2.x; asw[ 9*132+tid]=a2.y; asw[10*132+tid]=a2.z; asw[11*132+tid]=a2.w;
            asw[12*132+tid]=a3.x; asw[13*132+tid]=a3.y; asw[14*132+tid]=a3.z; asw[15*132+tid]=a3.w;
            float* bsw = Bs[nxt];
            bsw[(bkq+0)*68+brow]=b0.x; bsw[(bkq+1)*68+brow]=b0.y;
            bsw[(bkq+2)*68+brow]=b0.z; bsw[(bkq+3)*68+brow]=b0.w;
            bsw[(bkq+4)*68+brow]=b1.x; bsw[(bkq+5)*68+brow]=b1.y;
            bsw[(bkq+6)*68+brow]=b1.z; bsw[(bkq+7)*68+brow]=b1.w;
        }
        __syncthreads();
    }

#pragma unroll
    for (int i = 0; i < 8; i++) {
        int r = bm * 128 + ty * 8 + i;
#pragma unroll
        for (int j = 0; j < 8; j++) {
            int c = bn * 64 + tx * 8 + j;
            epi(r, c, acc[i][j] + bias[c]);
        }
    }
}

// ---------------- flash-style attention ----------------
// grid (5, 768), 256 threads. Streams K/V in 5 chunks of 64 with online softmax.
__global__ __launch_bounds__(256) void attn_kernel() {
    __shared__ float qT[32 * 68];   // [d][r]
    __shared__ float kT[32 * 68];   // [d][m]  (current chunk)
    __shared__ float vT[32 * 68];   // [d][m]
    __shared__ float ps[64 * 68];   // [r][m]
    __shared__ int   lab[64];

    int rtile = blockIdx.x, bh = blockIdx.y;
    int b_ = bh / 6, head = bh - b_ * 6;
    int tid = threadIdx.x;
    int tx = tid & 15, ty = tid >> 4;
    int lr = tid & 63, dg = (tid >> 6) * 8;

    const float* qrow = g_q + ((size_t)bh * NWIN + rtile * 64 + lr) * 32 + dg;
    const float* kp = g_k + (size_t)bh * NWIN * 32 + (size_t)lr * 32 + dg;
    const float* vp = g_v + (size_t)bh * NWIN * 32 + (size_t)lr * 32 + dg;

    {   // q load + transpose
        float4 a = *(const float4*)qrow;
        float4 b = *(const float4*)(qrow + 4);
        qT[(dg+0)*68+lr]=a.x; qT[(dg+1)*68+lr]=a.y; qT[(dg+2)*68+lr]=a.z; qT[(dg+3)*68+lr]=a.w;
        qT[(dg+4)*68+lr]=b.x; qT[(dg+5)*68+lr]=b.y; qT[(dg+6)*68+lr]=b.z; qT[(dg+7)*68+lr]=b.w;
    }
    if (tid < 64) {
        int w = b_ & 63;
        int wh = w >> 3, ww = w & 7;
        int i = tid >> 3, j = tid & 7;
        int hh = wh * 8 + i, wg = ww * 8 + j;
        int lh = hh < 56 ? 0 : (hh < 60 ? 1 : 2);
        int lw = wg < 56 ? 0 : (wg < 60 ? 1 : 2);
        lab[tid] = lh * 3 + lw;
    }
    // prefetch chunk 0
    float4 ka = *(const float4*)kp,     kb = *(const float4*)(kp + 4);
    float4 va = *(const float4*)vp,     vb = *(const float4*)(vp + 4);

    __syncthreads();
    int labm0 = lab[tx*4+0], labm1 = lab[tx*4+1], labm2 = lab[tx*4+2], labm3 = lab[tx*4+3];
    int labr[4];
#pragma unroll
    for (int i = 0; i < 4; i++) labr[i] = lab[ty*4+i];

    float mi[4], li[4], o0[4], o1[4];
#pragma unroll
    for (int i = 0; i < 4; i++) { mi[i] = -1e30f; li[i] = 0.f; o0[i] = 0.f; o1[i] = 0.f; }

    const float* bptr = g_bias6 + (size_t)head * (NWIN * NWIN) + (size_t)(rtile * 64) * NWIN;

    for (int c = 0; c < 5; c++) {
        __syncthreads();   // previous iteration finished reading kT/vT/ps
        kT[(dg+0)*68+lr]=ka.x; kT[(dg+1)*68+lr]=ka.y; kT[(dg+2)*68+lr]=ka.z; kT[(dg+3)*68+lr]=ka.w;
        kT[(dg+4)*68+lr]=kb.x; kT[(dg+5)*68+lr]=kb.y; kT[(dg+6)*68+lr]=kb.z; kT[(dg+7)*68+lr]=kb.w;
        vT[(dg+0)*68+lr]=va.x; vT[(dg+1)*68+lr]=va.y; vT[(dg+2)*68+lr]=va.z; vT[(dg+3)*68+lr]=va.w;
        vT[(dg+4)*68+lr]=vb.x; vT[(dg+5)*68+lr]=vb.y; vT[(dg+6)*68+lr]=vb.z; vT[(dg+7)*68+lr]=vb.w;
        if (c < 4) {
            kp += 64 * 32; vp += 64 * 32;
            ka = *(const float4*)kp; kb = *(const float4*)(kp + 4);
            va = *(const float4*)vp; vb = *(const float4*)(vp + 4);
        }
        __syncthreads();

        // S = q @ k^T (q pre-scaled)
        float acc[4][4] = {};
#pragma unroll
        for (int d = 0; d < 32; d++) {
            float4 qv = *(const float4*)&qT[d * 68 + ty * 4];
            float4 kv = *(const float4*)&kT[d * 68 + tx * 4];
            float qa[4] = {qv.x, qv.y, qv.z, qv.w};
            float kk4[4] = {kv.x, kv.y, kv.z, kv.w};
#pragma unroll
            for (int i = 0; i < 4; i++)
#pragma unroll
                for (int j = 0; j < 4; j++) acc[i][j] += qa[i] * kk4[j];
        }

        // bias + mask + online softmax; write P
#pragma unroll
        for (int i = 0; i < 4; i++) {
            int r = ty * 4 + i;
            float4 b4 = *(const float4*)(bptr + (size_t)r * NWIN + c * 64 + tx * 4);
            int lr_i = labr[i];
            float v0 = acc[i][0] + b4.x + (lr_i != labm0 ? -100.f : 0.f);
            float v1 = acc[i][1] + b4.y + (lr_i != labm1 ? -100.f : 0.f);
            float v2 = acc[i][2] + b4.z + (lr_i != labm2 ? -100.f : 0.f);
            float v3 = acc[i][3] + b4.w + (lr_i != labm3 ? -100.f : 0.f);
            float mloc = fmaxf(fmaxf(v0, v1), fmaxf(v2, v3));
#pragma unroll
            for (int off = 1; off < 16; off <<= 1)
                mloc = fmaxf(mloc, __shfl_xor_sync(0xffffffffu, mloc, off));
            float mnew = fmaxf(mi[i], mloc);
            float p0 = __expf(v0 - mnew), p1 = __expf(v1 - mnew);
            float p2 = __expf(v2 - mnew), p3 = __expf(v3 - mnew);
            float rs = (p0 + p1) + (p2 + p3);
#pragma unroll
            for (int off = 1; off < 16; off <<= 1)
                rs += __shfl_xor_sync(0xffffffffu, rs, off);
            float scale = __expf(mi[i] - mnew);
            li[i] = li[i] * scale + rs;
            o0[i] *= scale; o1[i] *= scale;
            mi[i] = mnew;
            *(float4*)&ps[r * 68 + tx * 4] = make_float4(p0, p1, p2, p3);
        }
        __syncthreads();

        // O += P @ V
#pragma unroll
        for (int m0 = 0; m0 < 64; m0 += 4) {
            float4 va4 = *(const float4*)&vT[tx * 68 + m0];
            float4 vb4 = *(const float4*)&vT[(tx + 16) * 68 + m0];
#pragma unroll
            for (int i = 0; i < 4; i++) {
                float4 p = *(const float4*)&ps[(ty * 4 + i) * 68 + m0];
                o0[i] += p.x * va4.x + p.y * va4.y + p.z * va4.z + p.w * va4.w;
                o1[i] += p.x * vb4.x + p.y * vb4.y + p.z * vb4.z + p.w * vb4.w;
            }
        }
    }

#pragma unroll
    for (int i = 0; i < 4; i++) {
        int gn = rtile * 64 + ty * 4 + i;
        float inv = 1.0f / li[i];
        size_t base = ((size_t)b_ * NWIN + gn) * CDIM + head * 32;
        g_a[base + tx]      = o0[i] * inv;
        g_a[base + tx + 16] = o1[i] * inv;
    }
}

// ---------------- launch ----------------
extern "C" void kernel_launch(void* const* d_in, const int* in_sizes, int n_in,
                              void* d_out, int out_size) {
    (void)in_sizes; (void)n_in; (void)out_size;
    const float* x      = (const float*)d_in[0];
    const float* ln1_g  = (const float*)d_in[1];
    const float* ln1_b  = (const float*)d_in[2];
    const float* qkv_w  = (const float*)d_in[3];
    const float* qkv_b  = (const float*)d_in[4];
    const float* table  = (const float*)d_in[5];
    const float* proj_w = (const float*)d_in[6];
    const float* proj_b = (const float*)d_in[7];
    const float* ln2_g  = (const float*)d_in[8];
    const float* ln2_b  = (const float*)d_in[9];
    const float* fc1_w  = (const float*)d_in[10];
    const float* fc1_b  = (const float*)d_in[11];
    const float* fc2_w  = (const float*)d_in[12];
    const float* fc2_b  = (const float*)d_in[13];
    float* out = (float*)d_out;

    bias_kernel<<<600, 1024>>>(table);
    ln_kernel<0><<<ROWS / 8, 256>>>(x, ln1_g, ln1_b);
    gemm128<1, true,  EpiQKV ><<<dim3(9, 320),  128>>>(nullptr, qkv_w,  qkv_b,  192, EpiQKV{});
    attn_kernel<<<dim3(5, BH), 256>>>();
    gemm128<2, false, EpiProj><<<dim3(3, 320),  128>>>(nullptr, proj_w, proj_b, 192, EpiProj{x});
    ln_kernel<1><<<ROWS / 8, 256>>>(nullptr, ln2_g, ln2_b);
    gemm128<1, false, EpiGelu><<<dim3(12, 320), 128>>>(nullptr, fc1_w,  fc1_b,  192, EpiGelu{});
    gemm128<3, false, EpiOut ><<<dim3(3, 320),  128>>>(nullptr, fc2_w,  fc2_b,  768, EpiOut{out});
}

// round 14
// speedup vs baseline: 2.1449x; 2.1449x over previous
#include <cuda_runtime.h>
#include <cuda_fp16.h>
#include <math.h>
#include <stdint.h>

// ---------------- problem constants ----------------
#define ROWS      40960
#define CDIM      192
#define NWIN      320
#define BH        768
#define MLPH      768
#define QK_SCALE  0.17677669529663687f

// ---------------- scratch ----------------
__device__ float g_h [ (size_t)ROWS * CDIM ];
__device__ float g_q [ (size_t)BH * NWIN * 32 ];
__device__ float g_k [ (size_t)BH * NWIN * 32 ];
__device__ float g_v [ (size_t)BH * NWIN * 32 ];
__device__ float g_a [ (size_t)ROWS * CDIM ];
__device__ float g_x1[ (size_t)ROWS * CDIM ];
__device__ float g_g [ (size_t)ROWS * MLPH ];
__device__ float g_bias6[ 6 * NWIN * NWIN ];
// fp16 weights
__device__ __half g_wq[576 * 192];
__device__ __half g_wp[192 * 192];
__device__ __half g_w1[768 * 192];
__device__ __half g_w2[192 * 768];

__device__ __forceinline__ int winmap(int wr) {
    int b_ = wr / NWIN, n = wr - b_ * NWIN;
    int b  = b_ >> 6,  w = b_ & 63;
    int wh = w >> 3,   ww = w & 7;
    int t  = n >> 6;
    int rem = n & 63;
    int i = rem >> 3, j = rem & 7;
    int hs = (wh * 8 + i + 4) & 63;
    int ws = (ww * 8 + j + 4) & 63;
    return ((b * 5 + t) << 12) + (hs << 6) + ws;
}

// ---------------- mma helpers (plain sm_80+ PTX, compiles for sm_103) -------
__device__ __forceinline__ uint32_t smem_u32(const void* p) {
    uint32_t a;
    asm("{ .reg .u64 t; cvta.to.shared.u64 t, %1; cvt.u32.u64 %0, t; }" : "=r"(a) : "l"(p));
    return a;
}
__device__ __forceinline__ void ldsm4(uint32_t* r, uint32_t a) {
    asm volatile("ldmatrix.sync.aligned.m8n8.x4.shared.b16 {%0,%1,%2,%3}, [%4];"
        : "=r"(r[0]), "=r"(r[1]), "=r"(r[2]), "=r"(r[3]) : "r"(a));
}
__device__ __forceinline__ void ldsm2(uint32_t* r, uint32_t a) {
    asm volatile("ldmatrix.sync.aligned.m8n8.x2.shared.b16 {%0,%1}, [%2];"
        : "=r"(r[0]), "=r"(r[1]) : "r"(a));
}
__device__ __forceinline__ void mma16816(float* c, const uint32_t* a, const uint32_t* b) {
    asm volatile("mma.sync.aligned.m16n8k16.row.col.f32.f16.f16.f32 "
        "{%0,%1,%2,%3}, {%4,%5,%6,%7}, {%8,%9}, {%0,%1,%2,%3};"
        : "+f"(c[0]), "+f"(c[1]), "+f"(c[2]), "+f"(c[3])
        : "r"(a[0]), "r"(a[1]), "r"(a[2]), "r"(a[3]), "r"(b[0]), "r"(b[1]));
}

// ---------------- weight fp16 conversion ----------------
template<int WSRC>
__global__ void cvt_kernel(const float* __restrict__ s, int n) {
    __half* d = (WSRC == 0) ? g_wq : (WSRC == 1) ? g_wp : (WSRC == 2) ? g_w1 : g_w2;
    int i = blockIdx.x * 256 + threadIdx.x;
    if (i < n) d[i] = __float2half(s[i]);
}

// ---------------- relative-position bias precompute ----------------
__global__ void bias_kernel(const float* __restrict__ table) {
    int e = blockIdx.x * 1024 + threadIdx.x;
    if (e >= 6 * NWIN * NWIN) return;
    int head = e / (NWIN * NWIN);
    int r = e - head * (NWIN * NWIN);
    int n = r / NWIN, m = r - n * NWIN;
    int t1 = n >> 6, p1 = n & 63, i1 = p1 >> 3, j1 = p1 & 7;
    int t2 = m >> 6, p2 = m & 63, i2 = p2 >> 3, j2 = p2 & 7;
    int idx = (t1 - t2 + 7) * 15 + (i1 - i2 + 7) + (j1 - j2);
    g_bias6[e] = table[idx * 6 + head];
}

// ---------------- LayerNorm ----------------
template<int SRC>
__global__ __launch_bounds__(256) void ln_kernel(const float* __restrict__ in,
                                                 const float* __restrict__ gw,
                                                 const float* __restrict__ bw) {
    int row  = blockIdx.x * 8 + (threadIdx.x >> 5);
    int lane = threadIdx.x & 31;
    const float* src = (SRC == 0) ? in : g_x1;
    const float* p = src + (size_t)row * CDIM;
    float v[6];
    float s = 0.f;
#pragma unroll
    for (int u = 0; u < 6; u++) { v[u] = p[lane + 32 * u]; s += v[u]; }
#pragma unroll
    for (int o = 16; o; o >>= 1) s += __shfl_xor_sync(0xffffffffu, s, o);
    float mu = s * (1.0f / CDIM);
    float q = 0.f;
#pragma unroll
    for (int u = 0; u < 6; u++) { float d = v[u] - mu; q += d * d; }
#pragma unroll
    for (int o = 16; o; o >>= 1) q += __shfl_xor_sync(0xffffffffu, q, o);
    float rs = rsqrtf(q * (1.0f / CDIM) + 1e-5f);
    float* o = g_h + (size_t)row * CDIM;
#pragma unroll
    for (int u = 0; u < 6; u++) {
        int c = lane + 32 * u;
        o[c] = (v[u] - mu) * rs * gw[c] + bw[c];
    }
}

// ---------------- GEMM epilogues ----------------
struct EpiQKV {
    __device__ void operator()(int wr, int oc, float val) const {
        int which = oc / CDIM;
        int rem = oc - which * CDIM;
        int h = rem >> 5, d = rem & 31;
        int b_ = wr / NWIN, n = wr - b_ * NWIN;
        size_t off = ((size_t)(b_ * 6 + h)) * (NWIN * 32) + (size_t)n * 32 + d;
        if (which == 0)      g_q[off] = val * QK_SCALE;
        else if (which == 1) g_k[off] = val;
        else                 g_v[off] = val;
    }
};
struct EpiProj {
    const float* x;
    __device__ void operator()(int wr, int c, float v) const {
        int dst = winmap(wr);
        size_t o = (size_t)dst * CDIM + c;
        g_x1[o] = x[o] + v;
    }
};
struct EpiGelu {
    __device__ void operator()(int r, int c, float v) const {
        g_g[(size_t)r * MLPH + c] = 0.5f * v * (1.0f + erff(v * 0.7071067811865476f));
    }
};
struct EpiOut {
    float* out;
    __device__ void operator()(int r, int c, float v) const {
        size_t o = (size_t)r * CDIM + c;
        out[o] = g_x1[o] + v;
    }
};

// ---------------- HMMA GEMM: 128(M) x 64(N) per CTA, K chunks of 64 ----------
// D = A(fp32->fp16) @ W(fp16)^T + bias, fp32 accum via mma.sync m16n8k16.
// smem rows: 64 fp16 = 128B, XOR-swizzled in 16B units by row%8.
template<int ASRC, int WSRC, bool GATHER, class Epi>
__global__ __launch_bounds__(256) void hgemm(const float* __restrict__ bias, int K, Epi epi) {
    __shared__ __align__(128) __half sA[128 * 64];
    __shared__ __align__(128) __half sW[64 * 64];
    const float* Asrc = (ASRC == 1) ? g_h : (ASRC == 2) ? g_a : g_g;
    const __half* Wb = (WSRC == 0) ? g_wq : (WSRC == 1) ? g_wp : (WSRC == 2) ? g_w1 : g_w2;

    int tid = threadIdx.x, lane = tid & 31, warp = tid >> 5;
    int bm = blockIdx.y, bn = blockIdx.x;
    int wm = (warp & 3) * 32, wn = (warp >> 2) * 32;
    uint32_t sAb = smem_u32(sA), sWb = smem_u32(sW);

    // per-thread load geometry (same for every chunk)
    int lrow = tid >> 3;            // 0..31
    int kq   = (tid & 7) * 8;       // fp16 col within 64
    int cb   = (kq * 2) ^ ((lrow & 7) << 4);   // swizzled byte col

    const float* Aptr[4];
#pragma unroll
    for (int i = 0; i < 4; i++) {
        int grow = bm * 128 + lrow + i * 32;
        int as = GATHER ? winmap(grow) : grow;
        Aptr[i] = Asrc + (size_t)as * K + kq;
    }
    const __half* Wptr[2];
#pragma unroll
    for (int i = 0; i < 2; i++)
        Wptr[i] = Wb + (size_t)(bn * 64 + lrow + i * 32) * K + kq;

    // ldmatrix lane addressing
    int aq = lane >> 3, ar = lane & 7;
    int a_row0 = wm + ar + (aq & 1) * 8;          // + mt*16
    int a_cbase = (aq >> 1) * 16;                  // + ks*32, then XOR
    int bl = lane & 15;
    int b_row0 = wn + (bl & 7);                    // + nt*8
    int b_cbase = ((bl >> 3) & 1) * 16;            // + ks*32

    float acc[2][4][4];
#pragma unroll
    for (int mt = 0; mt < 2; mt++)
#pragma unroll
        for (int nt = 0; nt < 4; nt++)
#pragma unroll
            for (int e = 0; e < 4; e++) acc[mt][nt][e] = 0.f;

    int nch = K >> 6;
    for (int ch = 0; ch < nch; ch++) {
        __syncthreads();
        int k0 = ch * 64;
#pragma unroll
        for (int i = 0; i < 4; i++) {
            float4 f0 = *(const float4*)(Aptr[i] + k0);
            float4 f1 = *(const float4*)(Aptr[i] + k0 + 4);
            __half2 h0 = __floats2half2_rn(f0.x, f0.y);
            __half2 h1 = __floats2half2_rn(f0.z, f0.w);
            __half2 h2 = __floats2half2_rn(f1.x, f1.y);
            __half2 h3 = __floats2half2_rn(f1.z, f1.w);
            uint4 u;
            u.x = *(uint32_t*)&h0; u.y = *(uint32_t*)&h1;
            u.z = *(uint32_t*)&h2; u.w = *(uint32_t*)&h3;
            *(uint4*)((char*)sA + (lrow + i * 32) * 128 + cb) = u;
        }
#pragma unroll
        for (int i = 0; i < 2; i++) {
            uint4 v = *(const uint4*)(Wptr[i] + k0);
            *(uint4*)((char*)sW + (lrow + i * 32) * 128 + cb) = v;
        }
        __syncthreads();

#pragma unroll
        for (int ks = 0; ks < 4; ks++) {
            int kb = ks * 32;
            uint32_t afr[2][4];
#pragma unroll
            for (int mt = 0; mt < 2; mt++) {
                int row = a_row0 + mt * 16;
                int c2 = (kb + a_cbase) ^ ((row & 7) << 4);
                ldsm4(afr[mt], sAb + row * 128 + c2);
            }
            uint32_t bfr[4][2];
#pragma unroll
            for (int nt = 0; nt < 4; nt++) {
                int row = b_row0 + nt * 8;
                int c2 = (kb + b_cbase) ^ ((row & 7) << 4);
                ldsm2(bfr[nt], sWb + row * 128 + c2);
            }
#pragma unroll
            for (int mt = 0; mt < 2; mt++)
#pragma unroll
                for (int nt = 0; nt < 4; nt++)
                    mma16816(acc[mt][nt], afr[mt], bfr[nt]);
        }
    }

    // epilogue: c0,c1 -> row g, cols cp,cp+1 ; c2,c3 -> row g+8
    int g = lane >> 2, cp = (lane & 3) * 2;
#pragma unroll
    for (int mt = 0; mt < 2; mt++) {
        int r0 = bm * 128 + wm + mt * 16 + g;
#pragma unroll
        for (int nt = 0; nt < 4; nt++) {
            int c0 = bn * 64 + wn + nt * 8 + cp;
            float b0 = bias[c0], b1 = bias[c0 + 1];
            epi(r0,     c0,     acc[mt][nt][0] + b0);
            epi(r0,     c0 + 1, acc[mt][nt][1] + b1);
            epi(r0 + 8, c0,     acc[mt][nt][2] + b0);
            epi(r0 + 8, c0 + 1, acc[mt][nt][3] + b1);
        }
    }
}

// ---------------- flash-style attention (unchanged) ----------------
__global__ __launch_bounds__(256) void attn_kernel() {
    __shared__ float qT[32 * 68];
    __shared__ float kT[32 * 68];
    __shared__ float vT[32 * 68];
    __shared__ float ps[64 * 68];
    __shared__ int   lab[64];

    int rtile = blockIdx.x, bh = blockIdx.y;
    int b_ = bh / 6, head = bh - b_ * 6;
    int tid = threadIdx.x;
    int tx = tid & 15, ty = tid >> 4;
    int lr = tid & 63, dg = (tid >> 6) * 8;

    const float* qrow = g_q + ((size_t)bh * NWIN + rtile * 64 + lr) * 32 + dg;
    const float* kp = g_k + (size_t)bh * NWIN * 32 + (size_t)lr * 32 + dg;
    const float* vp = g_v + (size_t)bh * NWIN * 32 + (size_t)lr * 32 + dg;

    {
        float4 a = *(const float4*)qrow;
        float4 b = *(const float4*)(qrow + 4);
        qT[(dg+0)*68+lr]=a.x; qT[(dg+1)*68+lr]=a.y; qT[(dg+2)*68+lr]=a.z; qT[(dg+3)*68+lr]=a.w;
        qT[(dg+4)*68+lr]=b.x; qT[(dg+5)*68+lr]=b.y; qT[(dg+6)*68+lr]=b.z; qT[(dg+7)*68+lr]=b.w;
    }
    if (tid < 64) {
        int w = b_ & 63;
        int wh = w >> 3, ww = w & 7;
        int i = tid >> 3, j = tid & 7;
        int hh = wh * 8 + i, wg = ww * 8 + j;
        int lh = hh < 56 ? 0 : (hh < 60 ? 1 : 2);
        int lw = wg < 56 ? 0 : (wg < 60 ? 1 : 2);
        lab[tid] = lh * 3 + lw;
    }
    float4 ka = *(const float4*)kp, kb = *(const float4*)(kp + 4);
    float4 va = *(const float4*)vp, vb = *(const float4*)(vp + 4);

    __syncthreads();
    int labm0 = lab[tx*4+0], labm1 = lab[tx*4+1], labm2 = lab[tx*4+2], labm3 = lab[tx*4+3];
    int labr[4];
#pragma unroll
    for (int i = 0; i < 4; i++) labr[i] = lab[ty*4+i];

    float mi[4], li[4], o0[4], o1[4];
#pragma unroll
    for (int i = 0; i < 4; i++) { mi[i] = -1e30f; li[i] = 0.f; o0[i] = 0.f; o1[i] = 0.f; }

    const float* bptr = g_bias6 + (size_t)head * (NWIN * NWIN) + (size_t)(rtile * 64) * NWIN;

    for (int c = 0; c < 5; c++) {
        __syncthreads();
        kT[(dg+0)*68+lr]=ka.x; kT[(dg+1)*68+lr]=ka.y; kT[(dg+2)*68+lr]=ka.z; kT[(dg+3)*68+lr]=ka.w;
        kT[(dg+4)*68+lr]=kb.x; kT[(dg+5)*68+lr]=kb.y; kT[(dg+6)*68+lr]=kb.z; kT[(dg+7)*68+lr]=kb.w;
        vT[(dg+0)*68+lr]=va.x; vT[(dg+1)*68+lr]=va.y; vT[(dg+2)*68+lr]=va.z; vT[(dg+3)*68+lr]=va.w;
        vT[(dg+4)*68+lr]=vb.x; vT[(dg+5)*68+lr]=vb.y; vT[(dg+6)*68+lr]=vb.z; vT[(dg+7)*68+lr]=vb.w;
        if (c < 4) {
            kp += 64 * 32; vp += 64 * 32;
            ka = *(const float4*)kp; kb = *(const float4*)(kp + 4);
            va = *(const float4*)vp; vb = *(const float4*)(vp + 4);
        }
        __syncthreads();

        float acc[4][4] = {};
#pragma unroll
        for (int d = 0; d < 32; d++) {
            float4 qv = *(const float4*)&qT[d * 68 + ty * 4];
            float4 kv = *(const float4*)&kT[d * 68 + tx * 4];
            float qa[4] = {qv.x, qv.y, qv.z, qv.w};
            float kk4[4] = {kv.x, kv.y, kv.z, kv.w};
#pragma unroll
            for (int i = 0; i < 4; i++)
#pragma unroll
                for (int j = 0; j < 4; j++) acc[i][j] += qa[i] * kk4[j];
        }

#pragma unroll
        for (int i = 0; i < 4; i++) {
            int r = ty * 4 + i;
            float4 b4 = *(const float4*)(bptr + (size_t)r * NWIN + c * 64 + tx * 4);
            int lr_i = labr[i];
            float v0 = acc[i][0] + b4.x + (lr_i != labm0 ? -100.f : 0.f);
            float v1 = acc[i][1] + b4.y + (lr_i != labm1 ? -100.f : 0.f);
            float v2 = acc[i][2] + b4.z + (lr_i != labm2 ? -100.f : 0.f);
            float v3 = acc[i][3] + b4.w + (lr_i != labm3 ? -100.f : 0.f);
            float mloc = fmaxf(fmaxf(v0, v1), fmaxf(v2, v3));
#pragma unroll
            for (int off = 1; off < 16; off <<= 1)
                mloc = fmaxf(mloc, __shfl_xor_sync(0xffffffffu, mloc, off));
            float mnew = fmaxf(mi[i], mloc);
            float p0 = __expf(v0 - mnew), p1 = __expf(v1 - mnew);
            float p2 = __expf(v2 - mnew), p3 = __expf(v3 - mnew);
            float rs = (p0 + p1) + (p2 + p3);
#pragma unroll
            for (int off = 1; off < 16; off <<= 1)
                rs += __shfl_xor_sync(0xffffffffu, rs, off);
            float scale = __expf(mi[i] - mnew);
            li[i] = li[i] * scale + rs;
            o0[i] *= scale; o1[i] *= scale;
            mi[i] = mnew;
            *(float4*)&ps[r * 68 + tx * 4] = make_float4(p0, p1, p2, p3);
        }
        __syncthreads();

#pragma unroll
        for (int m0 = 0; m0 < 64; m0 += 4) {
            float4 va4 = *(const float4*)&vT[tx * 68 + m0];
            float4 vb4 = *(const float4*)&vT[(tx + 16) * 68 + m0];
#pragma unroll
            for (int i = 0; i < 4; i++) {
                float4 p = *(const float4*)&ps[(ty * 4 + i) * 68 + m0];
                o0[i] += p.x * va4.x + p.y * va4.y + p.z * va4.z + p.w * va4.w;
                o1[i] += p.x * vb4.x + p.y * vb4.y + p.z * vb4.z + p.w * vb4.w;
            }
        }
    }

#pragma unroll
    for (int i = 0; i < 4; i++) {
        int gn = rtile * 64 + ty * 4 + i;
        float inv = 1.0f / li[i];
        size_t base = ((size_t)b_ * NWIN + gn) * CDIM + head * 32;
        g_a[base + tx]      = o0[i] * inv;
        g_a[base + tx + 16] = o1[i] * inv;
    }
}

// ---------------- launch ----------------
extern "C" void kernel_launch(void* const* d_in, const int* in_sizes, int n_in,
                              void* d_out, int out_size) {
    (void)in_sizes; (void)n_in; (void)out_size;
    const float* x      = (const float*)d_in[0];
    const float* ln1_g  = (const float*)d_in[1];
    const float* ln1_b  = (const float*)d_in[2];
    const float* qkv_w  = (const float*)d_in[3];
    const float* qkv_b  = (const float*)d_in[4];
    const float* table  = (const float*)d_in[5];
    const float* proj_w = (const float*)d_in[6];
    const float* proj_b = (const float*)d_in[7];
    const float* ln2_g  = (const float*)d_in[8];
    const float* ln2_b  = (const float*)d_in[9];
    const float* fc1_w  = (const float*)d_in[10];
    const float* fc1_b  = (const float*)d_in[11];
    const float* fc2_w  = (const float*)d_in[12];
    const float* fc2_b  = (const float*)d_in[13];
    float* out = (float*)d_out;

    cvt_kernel<0><<<(576 * 192 + 255) / 256, 256>>>(qkv_w, 576 * 192);
    cvt_kernel<1><<<(192 * 192 + 255) / 256, 256>>>(proj_w, 192 * 192);
    cvt_kernel<2><<<(768 * 192 + 255) / 256, 256>>>(fc1_w, 768 * 192);
    cvt_kernel<3><<<(192 * 768 + 255) / 256, 256>>>(fc2_w, 192 * 768);

    bias_kernel<<<600, 1024>>>(table);
    ln_kernel<0><<<ROWS / 8, 256>>>(x, ln1_g, ln1_b);
    hgemm<1, 0, true,  EpiQKV ><<<dim3(9, 320),  256>>>(qkv_b, 192, EpiQKV{});
    attn_kernel<<<dim3(5, BH), 256>>>();
    hgemm<2, 1, false, EpiProj><<<dim3(3, 320),  256>>>(proj_b, 192, EpiProj{x});
    ln_kernel<1><<<ROWS / 8, 256>>>(nullptr, ln2_g, ln2_b);
    hgemm<1, 2, false, EpiGelu><<<dim3(12, 320), 256>>>(fc1_b, 192, EpiGelu{});
    hgemm<3, 3, false, EpiOut ><<<dim3(3, 320),  256>>>(fc2_b, 768, EpiOut{out});
}

// round 15
// speedup vs baseline: 2.9984x; 1.3979x over previous
#include <cuda_runtime.h>
#include <cuda_fp16.h>
#include <math.h>
#include <stdint.h>

// ---------------- problem constants ----------------
#define ROWS      40960
#define CDIM      192
#define NWIN      320
#define BH        768
#define MLPH      768
#define QK_SCALE  0.17677669529663687f

// ---------------- scratch ----------------
__device__ float g_h [ (size_t)ROWS * CDIM ];
__device__ __half g_qh[ (size_t)BH * NWIN * 32 ];
__device__ __half g_kh[ (size_t)BH * NWIN * 32 ];
__device__ __half g_vh[ (size_t)BH * NWIN * 32 ];
__device__ float g_a [ (size_t)ROWS * CDIM ];
__device__ float g_x1[ (size_t)ROWS * CDIM ];
__device__ float g_g [ (size_t)ROWS * MLPH ];
__device__ float g_bias6[ 6 * NWIN * NWIN ];
// fp16 weights
__device__ __half g_wq[576 * 192];
__device__ __half g_wp[192 * 192];
__device__ __half g_w1[768 * 192];
__device__ __half g_w2[192 * 768];

__device__ __forceinline__ int winmap(int wr) {
    int b_ = wr / NWIN, n = wr - b_ * NWIN;
    int b  = b_ >> 6,  w = b_ & 63;
    int wh = w >> 3,   ww = w & 7;
    int t  = n >> 6;
    int rem = n & 63;
    int i = rem >> 3, j = rem & 7;
    int hs = (wh * 8 + i + 4) & 63;
    int ws = (ww * 8 + j + 4) & 63;
    return ((b * 5 + t) << 12) + (hs << 6) + ws;
}

// ---------------- mma helpers ----------------
__device__ __forceinline__ uint32_t smem_u32(const void* p) {
    uint32_t a;
    asm("{ .reg .u64 t; cvta.to.shared.u64 t, %1; cvt.u32.u64 %0, t; }" : "=r"(a) : "l"(p));
    return a;
}
__device__ __forceinline__ void ldsm4(uint32_t* r, uint32_t a) {
    asm volatile("ldmatrix.sync.aligned.m8n8.x4.shared.b16 {%0,%1,%2,%3}, [%4];"
        : "=r"(r[0]), "=r"(r[1]), "=r"(r[2]), "=r"(r[3]) : "r"(a));
}
__device__ __forceinline__ void ldsm2(uint32_t* r, uint32_t a) {
    asm volatile("ldmatrix.sync.aligned.m8n8.x2.shared.b16 {%0,%1}, [%2];"
        : "=r"(r[0]), "=r"(r[1]) : "r"(a));
}
__device__ __forceinline__ void mma16816(float* c, const uint32_t* a, const uint32_t* b) {
    asm volatile("mma.sync.aligned.m16n8k16.row.col.f32.f16.f16.f32 "
        "{%0,%1,%2,%3}, {%4,%5,%6,%7}, {%8,%9}, {%0,%1,%2,%3};"
        : "+f"(c[0]), "+f"(c[1]), "+f"(c[2]), "+f"(c[3])
        : "r"(a[0]), "r"(a[1]), "r"(a[2]), "r"(a[3]), "r"(b[0]), "r"(b[1]));
}

// ---------------- merged weight fp16 conversion ----------------
#define NWQ (576*192)
#define NWP (192*192)
#define NW1 (768*192)
#define NW2 (192*768)
__global__ void cvt_all(const float* __restrict__ qkvw, const float* __restrict__ projw,
                        const float* __restrict__ f1w, const float* __restrict__ f2w) {
    int i = blockIdx.x * 256 + threadIdx.x;
    if (i < NWQ) g_wq[i] = __float2half(qkvw[i]);
    else if (i < NWQ + NWP) g_wp[i - NWQ] = __float2half(projw[i - NWQ]);
    else if (i < NWQ + NWP + NW1) g_w1[i - NWQ - NWP] = __float2half(f1w[i - NWQ - NWP]);
    else if (i < NWQ + NWP + NW1 + NW2) g_w2[i - NWQ - NWP - NW1] = __float2half(f2w[i - NWQ - NWP - NW1]);
}

// ---------------- relative-position bias precompute ----------------
__global__ void bias_kernel(const float* __restrict__ table) {
    int e = blockIdx.x * 1024 + threadIdx.x;
    if (e >= 6 * NWIN * NWIN) return;
    int head = e / (NWIN * NWIN);
    int r = e - head * (NWIN * NWIN);
    int n = r / NWIN, m = r - n * NWIN;
    int t1 = n >> 6, p1 = n & 63, i1 = p1 >> 3, j1 = p1 & 7;
    int t2 = m >> 6, p2 = m & 63, i2 = p2 >> 3, j2 = p2 & 7;
    int idx = (t1 - t2 + 7) * 15 + (i1 - i2 + 7) + (j1 - j2);
    g_bias6[e] = table[idx * 6 + head];
}

// ---------------- LayerNorm ----------------
template<int SRC>
__global__ __launch_bounds__(256) void ln_kernel(const float* __restrict__ in,
                                                 const float* __restrict__ gw,
                                                 const float* __restrict__ bw) {
    int row  = blockIdx.x * 8 + (threadIdx.x >> 5);
    int lane = threadIdx.x & 31;
    const float* src = (SRC == 0) ? in : g_x1;
    const float* p = src + (size_t)row * CDIM;
    float v[6];
    float s = 0.f;
#pragma unroll
    for (int u = 0; u < 6; u++) { v[u] = p[lane + 32 * u]; s += v[u]; }
#pragma unroll
    for (int o = 16; o; o >>= 1) s += __shfl_xor_sync(0xffffffffu, s, o);
    float mu = s * (1.0f / CDIM);
    float q = 0.f;
#pragma unroll
    for (int u = 0; u < 6; u++) { float d = v[u] - mu; q += d * d; }
#pragma unroll
    for (int o = 16; o; o >>= 1) q += __shfl_xor_sync(0xffffffffu, q, o);
    float rs = rsqrtf(q * (1.0f / CDIM) + 1e-5f);
    float* o = g_h + (size_t)row * CDIM;
#pragma unroll
    for (int u = 0; u < 6; u++) {
        int c = lane + 32 * u;
        o[c] = (v[u] - mu) * rs * gw[c] + bw[c];
    }
}

// ---------------- GEMM epilogues ----------------
struct EpiQKV {
    __device__ void operator()(int wr, int oc, float val) const {
        int which = oc / CDIM;
        int rem = oc - which * CDIM;
        int h = rem >> 5, d = rem & 31;
        int b_ = wr / NWIN, n = wr - b_ * NWIN;
        size_t off = ((size_t)(b_ * 6 + h)) * (NWIN * 32) + (size_t)n * 32 + d;
        if (which == 0)      g_qh[off] = __float2half(val * QK_SCALE);
        else if (which == 1) g_kh[off] = __float2half(val);
        else                 g_vh[off] = __float2half(val);
    }
};
struct EpiProj {
    const float* x;
    __device__ void operator()(int wr, int c, float v) const {
        int dst = winmap(wr);
        size_t o = (size_t)dst * CDIM + c;
        g_x1[o] = x[o] + v;
    }
};
struct EpiGelu {
    __device__ void operator()(int r, int c, float v) const {
        g_g[(size_t)r * MLPH + c] = 0.5f * v * (1.0f + erff(v * 0.7071067811865476f));
    }
};
struct EpiOut {
    float* out;
    __device__ void operator()(int r, int c, float v) const {
        size_t o = (size_t)r * CDIM + c;
        out[o] = g_x1[o] + v;
    }
};

// ---------------- HMMA GEMM: 128(M) x 64(N) per CTA, K chunks of 64 ----------
template<int ASRC, int WSRC, bool GATHER, class Epi>
__global__ __launch_bounds__(256) void hgemm(const float* __restrict__ bias, int K, Epi epi) {
    __shared__ __align__(128) __half sA[128 * 64];
    __shared__ __align__(128) __half sW[64 * 64];
    const float* Asrc = (ASRC == 1) ? g_h : (ASRC == 2) ? g_a : g_g;
    const __half* Wb = (WSRC == 0) ? g_wq : (WSRC == 1) ? g_wp : (WSRC == 2) ? g_w1 : g_w2;

    int tid = threadIdx.x, lane = tid & 31, warp = tid >> 5;
    int bm = blockIdx.y, bn = blockIdx.x;
    int wm = (warp & 3) * 32, wn = (warp >> 2) * 32;
    uint32_t sAb = smem_u32(sA), sWb = smem_u32(sW);

    int lrow = tid >> 3;
    int kq   = (tid & 7) * 8;
    int cb   = (kq * 2) ^ ((lrow & 7) << 4);

    const float* Aptr[4];
#pragma unroll
    for (int i = 0; i < 4; i++) {
        int grow = bm * 128 + lrow + i * 32;
        int as = GATHER ? winmap(grow) : grow;
        Aptr[i] = Asrc + (size_t)as * K + kq;
    }
    const __half* Wptr[2];
#pragma unroll
    for (int i = 0; i < 2; i++)
        Wptr[i] = Wb + (size_t)(bn * 64 + lrow + i * 32) * K + kq;

    int aq = lane >> 3, ar = lane & 7;
    int a_row0 = wm + ar + (aq & 1) * 8;
    int a_cbase = (aq >> 1) * 16;
    int bl = lane & 15;
    int b_row0 = wn + (bl & 7);
    int b_cbase = ((bl >> 3) & 1) * 16;

    float acc[2][4][4];
#pragma unroll
    for (int mt = 0; mt < 2; mt++)
#pragma unroll
        for (int nt = 0; nt < 4; nt++)
#pragma unroll
            for (int e = 0; e < 4; e++) acc[mt][nt][e] = 0.f;

    int nch = K >> 6;
    for (int ch = 0; ch < nch; ch++) {
        __syncthreads();
        int k0 = ch * 64;
#pragma unroll
        for (int i = 0; i < 4; i++) {
            float4 f0 = *(const float4*)(Aptr[i] + k0);
            float4 f1 = *(const float4*)(Aptr[i] + k0 + 4);
            __half2 h0 = __floats2half2_rn(f0.x, f0.y);
            __half2 h1 = __floats2half2_rn(f0.z, f0.w);
            __half2 h2 = __floats2half2_rn(f1.x, f1.y);
            __half2 h3 = __floats2half2_rn(f1.z, f1.w);
            uint4 u;
            u.x = *(uint32_t*)&h0; u.y = *(uint32_t*)&h1;
            u.z = *(uint32_t*)&h2; u.w = *(uint32_t*)&h3;
            *(uint4*)((char*)sA + (lrow + i * 32) * 128 + cb) = u;
        }
#pragma unroll
        for (int i = 0; i < 2; i++) {
            uint4 v = *(const uint4*)(Wptr[i] + k0);
            *(uint4*)((char*)sW + (lrow + i * 32) * 128 + cb) = v;
        }
        __syncthreads();

#pragma unroll
        for (int ks = 0; ks < 4; ks++) {
            int kb = ks * 32;
            uint32_t afr[2][4];
#pragma unroll
            for (int mt = 0; mt < 2; mt++) {
                int row = a_row0 + mt * 16;
                int c2 = (kb + a_cbase) ^ ((row & 7) << 4);
                ldsm4(afr[mt], sAb + row * 128 + c2);
            }
            uint32_t bfr[4][2];
#pragma unroll
            for (int nt = 0; nt < 4; nt++) {
                int row = b_row0 + nt * 8;
                int c2 = (kb + b_cbase) ^ ((row & 7) << 4);
                ldsm2(bfr[nt], sWb + row * 128 + c2);
            }
#pragma unroll
            for (int mt = 0; mt < 2; mt++)
#pragma unroll
                for (int nt = 0; nt < 4; nt++)
                    mma16816(acc[mt][nt], afr[mt], bfr[nt]);
        }
    }

    int g = lane >> 2, cp = (lane & 3) * 2;
#pragma unroll
    for (int mt = 0; mt < 2; mt++) {
        int r0 = bm * 128 + wm + mt * 16 + g;
#pragma unroll
        for (int nt = 0; nt < 4; nt++) {
            int c0 = bn * 64 + wn + nt * 8 + cp;
            float b0 = bias[c0], b1 = bias[c0 + 1];
            epi(r0,     c0,     acc[mt][nt][0] + b0);
            epi(r0,     c0 + 1, acc[mt][nt][1] + b1);
            epi(r0 + 8, c0,     acc[mt][nt][2] + b0);
            epi(r0 + 8, c0 + 1, acc[mt][nt][3] + b1);
        }
    }
}

// ---------------- HMMA flash attention ----------------
// grid (5, 768), 128 threads (4 warps); warp w owns q rows [rtile*64+w*16, +16).
__global__ __launch_bounds__(128) void attn_kernel() {
    __shared__ __half qs[64 * 40];   // [row][d] rows 80B
    __shared__ __half ks[64 * 40];   // [key][d] (current chunk)
    __shared__ __half vT[32 * 72];   // [d][key] rows 144B
    __shared__ int    lab[64];

    int rtile = blockIdx.x, bh = blockIdx.y;
    int b_ = bh / 6, head = bh - b_ * 6;
    int tid = threadIdx.x, lane = tid & 31, warp = tid >> 5;
    int row6 = tid & 63, dhh = tid >> 6;   // global-load geometry

    {   // Q load (fp16, coalesced)
        const __half* qg = g_qh + ((size_t)bh * NWIN + rtile * 64 + row6) * 32 + dhh * 16;
        uint4 q0 = *(const uint4*)qg;
        uint4 q1 = *(const uint4*)(qg + 8);
        *(uint4*)((char*)qs + row6 * 80 + dhh * 32) = q0;
        *(uint4*)((char*)qs + row6 * 80 + dhh * 32 + 16) = q1;
    }
    if (tid < 64) {
        int w = b_ & 63;
        int wh = w >> 3, ww = w & 7;
        int i = tid >> 3, j = tid & 7;
        int hh = wh * 8 + i, wg = ww * 8 + j;
        int lh = hh < 56 ? 0 : (hh < 60 ? 1 : 2);
        int lw = wg < 56 ? 0 : (wg < 60 ? 1 : 2);
        lab[tid] = lh * 3 + lw;
    }
    const __half* kg = g_kh + ((size_t)bh * NWIN + row6) * 32 + dhh * 16;
    const __half* vg = g_vh + ((size_t)bh * NWIN + row6) * 32 + dhh * 16;
    uint4 ka0 = *(const uint4*)kg, ka1 = *(const uint4*)(kg + 8);
    uint4 va0 = *(const uint4*)vg, va1 = *(const uint4*)(vg + 8);

    __syncthreads();

    int wm = warp * 16, g = lane >> 2, qp = (lane & 3) * 2;
    uint32_t qa[2][4];
    {
        int ar = lane & 7, aq = lane >> 3;
        uint32_t base = smem_u32(qs) + (uint32_t)((wm + ar + (aq & 1) * 8) * 80 + (aq >> 1) * 16);
        ldsm4(qa[0], base);        // d 0..15
        ldsm4(qa[1], base + 32);   // d 16..31
    }
    // per-row mask bitmaps over 64 window-local keys
    int labr0 = lab[wm + g], labr1 = lab[wm + g + 8];
    uint64_t m0 = 0, m1 = 0;
    for (int k2 = 0; k2 < 64; k2++) {
        int lk = lab[k2];
        m0 |= (uint64_t)(lk != labr0) << k2;
        m1 |= (uint64_t)(lk != labr1) << k2;
    }

    float mi0 = -1e30f, mi1 = -1e30f, li0 = 0.f, li1 = 0.f;
    float o[4][4] = {};
    const float* bpr0 = g_bias6 + (size_t)head * (NWIN * NWIN) + (size_t)(rtile * 64 + wm + g) * NWIN;
    const float* bpr1 = bpr0 + 8 * NWIN;
    uint32_t ksb = smem_u32(ks);
    int bl = lane & 15;

    for (int c = 0; c < 5; c++) {
        __syncthreads();
        // store K chunk [key][d]
        *(uint4*)((char*)ks + row6 * 80 + dhh * 32) = ka0;
        *(uint4*)((char*)ks + row6 * 80 + dhh * 32 + 16) = ka1;
        // store V chunk transposed -> vT[d][key]
        {
            __half vh[16];
            *(uint4*)&vh[0] = va0; *(uint4*)&vh[8] = va1;
#pragma unroll
            for (int j = 0; j < 16; j++)
                vT[(dhh * 16 + j) * 72 + row6] = vh[j];
        }
        if (c < 4) {
            kg += 64 * 32; vg += 64 * 32;
            ka0 = *(const uint4*)kg; ka1 = *(const uint4*)(kg + 8);
            va0 = *(const uint4*)vg; va1 = *(const uint4*)(vg + 8);
        }
        __syncthreads();

        // S = Q K^T  (16x64 per warp)
        float s[8][4];
#pragma unroll
        for (int nt = 0; nt < 8; nt++) {
            s[nt][0] = s[nt][1] = s[nt][2] = s[nt][3] = 0.f;
            uint32_t kaddr = ksb + (uint32_t)((nt * 8 + (bl & 7)) * 80 + ((bl >> 3) & 1) * 16);
            uint32_t kb[2], kb2[2];
            ldsm2(kb,  kaddr);        // d 0-15
            ldsm2(kb2, kaddr + 32);   // d 16-31
            mma16816(s[nt], qa[0], kb);
            mma16816(s[nt], qa[1], kb2);
        }
        // bias + mask
#pragma unroll
        for (int nt = 0; nt < 8; nt++) {
            int kloc = nt * 8 + qp;
            float2 b0 = *(const float2*)(bpr0 + c * 64 + kloc);
            float2 b1 = *(const float2*)(bpr1 + c * 64 + kloc);
            s[nt][0] += b0.x + (((m0 >> kloc) & 1) ? -100.f : 0.f);
            s[nt][1] += b0.y + (((m0 >> (kloc + 1)) & 1) ? -100.f : 0.f);
            s[nt][2] += b1.x + (((m1 >> kloc) & 1) ? -100.f : 0.f);
            s[nt][3] += b1.y + (((m1 >> (kloc + 1)) & 1) ? -100.f : 0.f);
        }
        // online softmax on fragments (rows g, g+8; 4-lane quads)
        float mx0 = -1e30f, mx1 = -1e30f;
#pragma unroll
        for (int nt = 0; nt < 8; nt++) {
            mx0 = fmaxf(mx0, fmaxf(s[nt][0], s[nt][1]));
            mx1 = fmaxf(mx1, fmaxf(s[nt][2], s[nt][3]));
        }
        mx0 = fmaxf(mx0, __shfl_xor_sync(0xffffffffu, mx0, 1));
        mx0 = fmaxf(mx0, __shfl_xor_sync(0xffffffffu, mx0, 2));
        mx1 = fmaxf(mx1, __shfl_xor_sync(0xffffffffu, mx1, 1));
        mx1 = fmaxf(mx1, __shfl_xor_sync(0xffffffffu, mx1, 2));
        float mn0 = fmaxf(mi0, mx0), mn1 = fmaxf(mi1, mx1);
        uint32_t pa[8], pb[8];
        float l0 = 0.f, l1 = 0.f;
#pragma unroll
        for (int nt = 0; nt < 8; nt++) {
            float p0 = __expf(s[nt][0] - mn0), p1 = __expf(s[nt][1] - mn0);
            float p2 = __expf(s[nt][2] - mn1), p3 = __expf(s[nt][3] - mn1);
            l0 += p0 + p1; l1 += p2 + p3;
            __half2 h0 = __floats2half2_rn(p0, p1);
            __half2 h1 = __floats2half2_rn(p2, p3);
            pa[nt] = *(uint32_t*)&h0; pb[nt] = *(uint32_t*)&h1;
        }
        l0 += __shfl_xor_sync(0xffffffffu, l0, 1);
        l0 += __shfl_xor_sync(0xffffffffu, l0, 2);
        l1 += __shfl_xor_sync(0xffffffffu, l1, 1);
        l1 += __shfl_xor_sync(0xffffffffu, l1, 2);
        float sc0 = __expf(mi0 - mn0), sc1 = __expf(mi1 - mn1);
        li0 = li0 * sc0 + l0; li1 = li1 * sc1 + l1;
        mi0 = mn0; mi1 = mn1;
#pragma unroll
        for (int nt2 = 0; nt2 < 4; nt2++) {
            o[nt2][0] *= sc0; o[nt2][1] *= sc0;
            o[nt2][2] *= sc1; o[nt2][3] *= sc1;
        }
        // O += P V  (P fragments reused directly as A operands)
#pragma unroll
        for (int ks4 = 0; ks4 < 4; ks4++) {
            uint32_t af[4] = {pa[2 * ks4], pb[2 * ks4], pa[2 * ks4 + 1], pb[2 * ks4 + 1]};
#pragma unroll
            for (int nt2 = 0; nt2 < 4; nt2++) {
                uint32_t bv[2];
                bv[0] = *(const uint32_t*)((char*)vT + ((nt2 * 8 + g) * 72 + ks4 * 16 + qp) * 2);
                bv[1] = *(const uint32_t*)((char*)vT + ((nt2 * 8 + g) * 72 + ks4 * 16 + 8 + qp) * 2);
                mma16816(o[nt2], af, bv);
            }
        }
    }

    float inv0 = 1.f / li0, inv1 = 1.f / li1;
    int rn0 = rtile * 64 + wm + g;
    size_t base = ((size_t)b_ * NWIN + rn0) * CDIM + head * 32 + qp;
#pragma unroll
    for (int nt2 = 0; nt2 < 4; nt2++) {
        *(float2*)(g_a + base + nt2 * 8) = make_float2(o[nt2][0] * inv0, o[nt2][1] * inv0);
        *(float2*)(g_a + base + 8 * CDIM + nt2 * 8) = make_float2(o[nt2][2] * inv1, o[nt2][3] * inv1);
    }
}

// ---------------- launch ----------------
extern "C" void kernel_launch(void* const* d_in, const int* in_sizes, int n_in,
                              void* d_out, int out_size) {
    (void)in_sizes; (void)n_in; (void)out_size;
    const float* x      = (const float*)d_in[0];
    const float* ln1_g  = (const float*)d_in[1];
    const float* ln1_b  = (const float*)d_in[2];
    const float* qkv_w  = (const float*)d_in[3];
    const float* qkv_b  = (const float*)d_in[4];
    const float* table  = (const float*)d_in[5];
    const float* proj_w = (const float*)d_in[6];
    const float* proj_b = (const float*)d_in[7];
    const float* ln2_g  = (const float*)d_in[8];
    const float* ln2_b  = (const float*)d_in[9];
    const float* fc1_w  = (const float*)d_in[10];
    const float* fc1_b  = (const float*)d_in[11];
    const float* fc2_w  = (const float*)d_in[12];
    const float* fc2_b  = (const float*)d_in[13];
    float* out = (float*)d_out;

    cvt_all<<<(NWQ + NWP + NW1 + NW2 + 255) / 256, 256>>>(qkv_w, proj_w, fc1_w, fc2_w);
    bias_kernel<<<600, 1024>>>(table);
    ln_kernel<0><<<ROWS / 8, 256>>>(x, ln1_g, ln1_b);
    hgemm<1, 0, true,  EpiQKV ><<<dim3(9, 320),  256>>>(qkv_b, 192, EpiQKV{});
    attn_kernel<<<dim3(5, BH), 128>>>();
    hgemm<2, 1, false, EpiProj><<<dim3(3, 320),  256>>>(proj_b, 192, EpiProj{x});
    ln_kernel<1><<<ROWS / 8, 256>>>(nullptr, ln2_g, ln2_b);
    hgemm<1, 2, false, EpiGelu><<<dim3(12, 320), 256>>>(fc1_b, 192, EpiGelu{});
    hgemm<3, 3, false, EpiOut ><<<dim3(3, 320),  256>>>(fc2_b, 768, EpiOut{out});
}